// round 3
// baseline (speedup 1.0000x reference)
#include <cuda_runtime.h>
#include <cstdint>

#define N_NODES 100000
#define N_EDGES 600000
#define N_FEAT  128

// Scratch (device globals — no allocation allowed). 16B alignment is
// load-bearing for red.global.add.v4.f32.
__device__ __align__(16) float g_deg[N_NODES];
__device__ __align__(16) float g_dinv[N_NODES];
__device__ __align__(16) float g_aggx[(size_t)N_NODES * N_FEAT];
__device__ int g_src[N_EDGES];
__device__ int g_dst[N_EDGES];
__device__ unsigned int g_or;   // dtype-detection accumulator

// ---------------- edge_index dtype detection + decode ----------------
// Safe under BOTH layouts: reads only the first 1,200,000 int32 words
// (= full buffer if int32, first half if int64).
__global__ void k_or_init() { if (threadIdx.x == 0 && blockIdx.x == 0) g_or = 0u; }

__global__ void k_scan_odd(const unsigned int* __restrict__ w) {
    int i = blockIdx.x * blockDim.x + threadIdx.x;   // 600000 threads
    unsigned int v = 0u;
    if (i < N_EDGES) v = w[2 * i + 1];               // odd words
#pragma unroll
    for (int s = 16; s > 0; s >>= 1) v |= __shfl_xor_sync(0xffffffffu, v, s);
    if ((threadIdx.x & 31) == 0 && v) atomicOr(&g_or, v);
}

__global__ void k_decode(const int* __restrict__ w) {
    int i = blockIdx.x * blockDim.x + threadIdx.x;
    if (i >= N_EDGES) return;
    int s, d;
    if (g_or == 0u) {            // int64 layout: low word of each element
        s = w[2 * i];
        d = w[2 * (N_EDGES + i)];
    } else {                     // int32 layout
        s = w[i];
        d = w[N_EDGES + i];
    }
    // clamp: wrong detection degrades to rel_err, never to IMA
    s = min(max(s, 0), N_NODES - 1);
    d = min(max(d, 0), N_NODES - 1);
    g_src[i] = s;
    g_dst[i] = d;
}

// ---------------- degree ----------------
__global__ void k_deg_init() {
    int i = blockIdx.x * blockDim.x + threadIdx.x;
    if (i < N_NODES) g_deg[i] = 1.0f;  // self-loop pre-counted
}

__global__ void k_deg_scatter() {
    int i = blockIdx.x * blockDim.x + threadIdx.x;
    if (i < N_EDGES) atomicAdd(&g_deg[g_dst[i]], 1.0f);
}

__global__ void k_dinv() {
    int i = blockIdx.x * blockDim.x + threadIdx.x;
    if (i < N_NODES) g_dinv[i] = rsqrtf(g_deg[i]);  // deg >= 1 always
}

// ---------------- init aggx = x * dinv^2 (self-loop term) ----------------
__global__ void k_init_aggx(const float4* __restrict__ x4) {
    int t = blockIdx.x * blockDim.x + threadIdx.x;  // N*32 threads
    if (t < N_NODES * 32) {
        int node = t >> 5;
        float di = g_dinv[node];
        float s = di * di;
        float4 v = x4[t];
        v.x *= s; v.y *= s; v.z *= s; v.w *= s;
        ((float4*)g_aggx)[t] = v;
    }
}

// ---------------- edge scatter: aggx[dst] += x[src] * norm ----------------
__global__ void k_edge_scatter(const float4* __restrict__ x4) {
    int t = blockIdx.x * blockDim.x + threadIdx.x;
    int e = t >> 5;
    if (e >= N_EDGES) return;
    int lane = t & 31;
    int s = g_src[e];
    int d = g_dst[e];
    float norm = g_dinv[s] * g_dinv[d];
    float4 v = x4[s * 32 + lane];
    v.x *= norm; v.y *= norm; v.z *= norm; v.w *= norm;
    float* p = &g_aggx[(size_t)d * N_FEAT + lane * 4];
    asm volatile("red.global.add.v4.f32 [%0], {%1, %2, %3, %4};"
                 :: "l"(p), "f"(v.x), "f"(v.y), "f"(v.z), "f"(v.w)
                 : "memory");
}

// ---------------- GEMM: out = relu(aggx @ W + b), 128x128 tile/block ------
__global__ void __launch_bounds__(256, 2)
k_gemm_relu(const float* __restrict__ W, const float* __restrict__ b,
            float* __restrict__ out) {
    extern __shared__ float sm[];
    float* Ws = sm;               // 128*128 floats (full W)
    float* As = sm + 128 * 128;   // 8 x 132 (transposed A chunk, padded)

    int t = threadIdx.x;

    // stage full W into shared (coalesced float4)
    const float4* W4  = (const float4*)W;
    float4*       Ws4 = (float4*)Ws;
#pragma unroll
    for (int i = 0; i < 16; i++) Ws4[t + i * 256] = W4[t + i * 256];

    int row_base = blockIdx.x * 128;
    int tx = t & 15, ty = t >> 4;
    int r0 = ty * 8, c0 = tx * 8;

    float acc[8][8];
#pragma unroll
    for (int i = 0; i < 8; i++)
#pragma unroll
        for (int j = 0; j < 8; j++) acc[i][j] = 0.0f;

    const float4* A4 = (const float4*)g_aggx;
    int r = t >> 1, half = t & 1;
    int grow = row_base + r;
    if (grow >= N_NODES) grow = N_NODES - 1;  // clamp (stores are guarded)

    for (int kc = 0; kc < 128; kc += 8) {
        __syncthreads();
        // load A chunk [128 rows x 8 k] transposed into As[k][row]
        float4 v = A4[(size_t)grow * 32 + (kc >> 2) + half];
        int kb = half * 4;
        As[(kb + 0) * 132 + r] = v.x;
        As[(kb + 1) * 132 + r] = v.y;
        As[(kb + 2) * 132 + r] = v.z;
        As[(kb + 3) * 132 + r] = v.w;
        __syncthreads();

#pragma unroll
        for (int kk = 0; kk < 8; kk++) {
            float4 a0 = *(const float4*)&As[kk * 132 + r0];
            float4 a1 = *(const float4*)&As[kk * 132 + r0 + 4];
            float4 b0 = *(const float4*)&Ws[(kc + kk) * 128 + c0];
            float4 b1 = *(const float4*)&Ws[(kc + kk) * 128 + c0 + 4];
            float av[8] = {a0.x, a0.y, a0.z, a0.w, a1.x, a1.y, a1.z, a1.w};
            float bv[8] = {b0.x, b0.y, b0.z, b0.w, b1.x, b1.y, b1.z, b1.w};
#pragma unroll
            for (int i = 0; i < 8; i++)
#pragma unroll
                for (int j = 0; j < 8; j++) acc[i][j] += av[i] * bv[j];
        }
    }

    float4 bb0 = *(const float4*)&b[c0];
    float4 bb1 = *(const float4*)&b[c0 + 4];
#pragma unroll
    for (int i = 0; i < 8; i++) {
        int row = row_base + r0 + i;
        if (row < N_NODES) {
            float4 o0, o1;
            o0.x = fmaxf(acc[i][0] + bb0.x, 0.0f);
            o0.y = fmaxf(acc[i][1] + bb0.y, 0.0f);
            o0.z = fmaxf(acc[i][2] + bb0.z, 0.0f);
            o0.w = fmaxf(acc[i][3] + bb0.w, 0.0f);
            o1.x = fmaxf(acc[i][4] + bb1.x, 0.0f);
            o1.y = fmaxf(acc[i][5] + bb1.y, 0.0f);
            o1.z = fmaxf(acc[i][6] + bb1.z, 0.0f);
            o1.w = fmaxf(acc[i][7] + bb1.w, 0.0f);
            *(float4*)&out[(size_t)row * 128 + c0]     = o0;
            *(float4*)&out[(size_t)row * 128 + c0 + 4] = o1;
        }
    }
}

extern "C" void kernel_launch(void* const* d_in, const int* in_sizes, int n_in,
                              void* d_out, int out_size) {
    // Resolve inputs by element count (robust to ordering):
    //   x: 12,800,000 fp32 | W: 16,384 fp32 | b: 128 fp32
    //   edge_index: 1,200,000 elements (int32 OR int64 — detected on device)
    const float* x  = nullptr;
    const float* W  = nullptr;
    const float* b  = nullptr;
    const void*  ei = nullptr;
    for (int i = 0; i < n_in; i++) {
        switch (in_sizes[i]) {
            case 12800000: x  = (const float*)d_in[i]; break;
            case 16384:    W  = (const float*)d_in[i]; break;
            case 128:      b  = (const float*)d_in[i]; break;
            case 1200000:  ei = d_in[i];               break;
            default: break;
        }
    }
    float* out = (float*)d_out;
    (void)out_size;
    if (!x || !W || !b || !ei) return;

    // detect edge_index dtype, decode to int32 src/dst (clamped)
    k_or_init<<<1, 32>>>();
    k_scan_odd<<<(N_EDGES + 255) / 256, 256>>>((const unsigned int*)ei);
    k_decode<<<(N_EDGES + 255) / 256, 256>>>((const int*)ei);

    // degree (with self-loops) and dinv
    k_deg_init<<<(N_NODES + 255) / 256, 256>>>();
    k_deg_scatter<<<(N_EDGES + 255) / 256, 256>>>();
    k_dinv<<<(N_NODES + 255) / 256, 256>>>();

    // aggx = x * dinv^2   (self-loop contribution)
    {
        long long total = (long long)N_NODES * 32;
        k_init_aggx<<<(int)((total + 255) / 256), 256>>>((const float4*)x);
    }

    // aggx[dst] += x[src] * dinv[src]*dinv[dst]   (warp per edge, red.v4)
    {
        long long total = (long long)N_EDGES * 32;
        k_edge_scatter<<<(int)((total + 255) / 256), 256>>>((const float4*)x);
    }

    // out = relu(aggx @ W + b)
    {
        int smem = (128 * 128 + 8 * 132) * (int)sizeof(float);
        cudaFuncSetAttribute(k_gemm_relu,
                             cudaFuncAttributeMaxDynamicSharedMemorySize, smem);
        k_gemm_relu<<<(N_NODES + 127) / 128, 256, smem>>>(W, b, out);
    }
}

// round 4
// speedup vs baseline: 1.0275x; 1.0275x over previous
#include <cuda_runtime.h>
#include <cuda_bf16.h>
#include <cstdint>

#define N_NODES 100000
#define N_EDGES 600000
#define N_FEAT  128
#define NBLK    ((N_NODES + 127) / 128)   // 782

// Scratch (device globals — no allocation allowed). 16B alignment is
// load-bearing for red.global.add.v4.f32.
__device__ __align__(16) float g_deg[N_NODES];
__device__ __align__(16) float g_dinv[N_NODES];
__device__ __align__(16) float g_aggx[(size_t)N_NODES * N_FEAT];
__device__ int g_src[N_EDGES];
__device__ int g_dst[N_EDGES];
__device__ unsigned int g_or;   // dtype-detection accumulator
// W split into bf16 hi/lo, pre-swizzled into m16n8k16 B-fragment order:
// frag chunk (n, kstep, t) -> 4 bf16 {k=2t, 2t+1, 2t+8, 2t+9} = one uint2.
__device__ __align__(16) uint2 g_wfragH[128 * 8 * 4];
__device__ __align__(16) uint2 g_wfragL[128 * 8 * 4];

// ---------------- edge_index dtype detection + decode ----------------
__global__ void k_or_init() { if (threadIdx.x == 0 && blockIdx.x == 0) g_or = 0u; }

__global__ void k_scan_odd(const unsigned int* __restrict__ w) {
    int i = blockIdx.x * blockDim.x + threadIdx.x;   // 600000 threads
    unsigned int v = 0u;
    if (i < N_EDGES) v = w[2 * i + 1];               // odd words
#pragma unroll
    for (int s = 16; s > 0; s >>= 1) v |= __shfl_xor_sync(0xffffffffu, v, s);
    if ((threadIdx.x & 31) == 0 && v) atomicOr(&g_or, v);
}

__global__ void k_deg_init() {
    int i = blockIdx.x * blockDim.x + threadIdx.x;
    if (i < N_NODES) g_deg[i] = 1.0f;  // self-loop pre-counted
}

// decode + degree scatter fused (deg must be pre-initialized to 1.0)
__global__ void k_decode_deg(const int* __restrict__ w) {
    int i = blockIdx.x * blockDim.x + threadIdx.x;
    if (i >= N_EDGES) return;
    int s, d;
    if (g_or == 0u) {            // int64 layout: low word of each element
        s = w[2 * i];
        d = w[2 * (N_EDGES + i)];
    } else {                     // int32 layout
        s = w[i];
        d = w[N_EDGES + i];
    }
    s = min(max(s, 0), N_NODES - 1);
    d = min(max(d, 0), N_NODES - 1);
    g_src[i] = s;
    g_dst[i] = d;
    atomicAdd(&g_deg[d], 1.0f);
}

__global__ void k_dinv() {
    int i = blockIdx.x * blockDim.x + threadIdx.x;
    if (i < N_NODES) g_dinv[i] = rsqrtf(g_deg[i]);  // deg >= 1 always
}

// ---------------- init aggx = x * dinv^2 (self-loop term) ----------------
__global__ void k_init_aggx(const float4* __restrict__ x4) {
    int t = blockIdx.x * blockDim.x + threadIdx.x;  // N*32 threads
    if (t < N_NODES * 32) {
        int node = t >> 5;
        float di = g_dinv[node];
        float s = di * di;
        float4 v = x4[t];
        v.x *= s; v.y *= s; v.z *= s; v.w *= s;
        ((float4*)g_aggx)[t] = v;
    }
}

// ---------------- edge scatter: aggx[dst] += x[src] * norm ----------------
__global__ void k_edge_scatter(const float4* __restrict__ x4) {
    int t = blockIdx.x * blockDim.x + threadIdx.x;
    int e = t >> 5;
    if (e >= N_EDGES) return;
    int lane = t & 31;
    int s = g_src[e];
    int d = g_dst[e];
    float norm = g_dinv[s] * g_dinv[d];
    float4 v = x4[s * 32 + lane];
    v.x *= norm; v.y *= norm; v.z *= norm; v.w *= norm;
    float* p = &g_aggx[(size_t)d * N_FEAT + lane * 4];
    asm volatile("red.global.add.v4.f32 [%0], {%1, %2, %3, %4};"
                 :: "l"(p), "f"(v.x), "f"(v.y), "f"(v.z), "f"(v.w)
                 : "memory");
}

// ---------------- W split prep: fp32 -> bf16 hi/lo, fragment-order -------
__global__ void k_wsplit(const float* __restrict__ W) {
    int i = blockIdx.x * blockDim.x + threadIdx.x;   // 16384
    if (i >= 128 * 128) return;
    int k = i >> 7, n = i & 127;                     // W[k][n], k = in-feature
    float v = W[i];
    __nv_bfloat16 h = __float2bfloat16_rn(v);
    __nv_bfloat16 l = __float2bfloat16_rn(v - __bfloat162float(h));
    int kstep = k >> 4, kk = k & 15;
    int t = (kk & 7) >> 1;
    int idx4 = (kk < 8) ? (kk & 1) : (2 + (kk & 1));
    int base = (n * 8 + kstep) * 4 + t;
    ((__nv_bfloat16*)g_wfragH)[base * 4 + idx4] = h;
    ((__nv_bfloat16*)g_wfragL)[base * 4 + idx4] = l;
}

// ---------------- GEMM: out = relu(aggx @ W + b) via bf16x3 mma ----------
#define MMA_BF16(d, a0, a1, a2, a3, b0, b1)                                 \
    asm volatile(                                                           \
        "mma.sync.aligned.m16n8k16.row.col.f32.bf16.bf16.f32 "              \
        "{%0,%1,%2,%3}, {%4,%5,%6,%7}, {%8,%9}, {%0,%1,%2,%3};"             \
        : "+f"(d[0]), "+f"(d[1]), "+f"(d[2]), "+f"(d[3])                    \
        : "r"(a0), "r"(a1), "r"(a2), "r"(a3), "r"(b0), "r"(b1))

// smem layout (bytes): WfH [0,32768) | WfL [32768,65536)
//                      Ah  [65536, +33792) | Al (+33792)
#define SM_WFH 0
#define SM_WFL 32768
#define SM_AH  65536
#define SM_AL  (65536 + 33792)
#define SM_TOTAL (65536 + 2 * 33792)   // 133,120 B

__global__ void __launch_bounds__(256, 1)
k_gemm_relu(const float* __restrict__ b, float* __restrict__ out) {
    extern __shared__ char sm[];
    uint2* WfH = (uint2*)(sm + SM_WFH);
    uint2* WfL = (uint2*)(sm + SM_WFL);
    __nv_bfloat16* Ah = (__nv_bfloat16*)(sm + SM_AH);  // [128][132]
    __nv_bfloat16* Al = (__nv_bfloat16*)(sm + SM_AL);

    int tid = threadIdx.x;

    // stage W fragments (4096 uint2 each)
#pragma unroll
    for (int i = 0; i < 16; i++) {
        WfH[tid + i * 256] = g_wfragH[tid + i * 256];
        WfL[tid + i * 256] = g_wfragL[tid + i * 256];
    }

    // stage A tile: convert fp32 -> bf16 hi/lo
    int rowbase = blockIdx.x * 128;
    const float4* A4 = (const float4*)g_aggx;
#pragma unroll
    for (int i = 0; i < 16; i++) {
        int idx = tid + i * 256;          // 0..4095 (float4 units)
        int r   = idx >> 5;               // 0..127
        int c4  = (idx & 31) * 4;
        int grow = min(rowbase + r, N_NODES - 1);
        float4 v = A4[(size_t)grow * 32 + (idx & 31)];
        float vs[4] = {v.x, v.y, v.z, v.w};
#pragma unroll
        for (int j = 0; j < 4; j++) {
            __nv_bfloat16 h = __float2bfloat16_rn(vs[j]);
            Ah[r * 132 + c4 + j] = h;
            Al[r * 132 + c4 + j] = __float2bfloat16_rn(vs[j] - __bfloat162float(h));
        }
    }
    __syncthreads();

    int warp = tid >> 5, lane = tid & 31;
    int g = lane >> 2, t = lane & 3;
    int r0 = warp * 16 + g;   // row within block tile
    int r1 = r0 + 8;

    float acc[16][4];
#pragma unroll
    for (int nt = 0; nt < 16; nt++)
#pragma unroll
        for (int j = 0; j < 4; j++) acc[nt][j] = 0.0f;

#pragma unroll
    for (int ks = 0; ks < 8; ks++) {
        int k0 = ks * 16;
        uint32_t ah0 = *(const uint32_t*)&Ah[r0 * 132 + k0 + 2 * t];
        uint32_t ah1 = *(const uint32_t*)&Ah[r1 * 132 + k0 + 2 * t];
        uint32_t ah2 = *(const uint32_t*)&Ah[r0 * 132 + k0 + 2 * t + 8];
        uint32_t ah3 = *(const uint32_t*)&Ah[r1 * 132 + k0 + 2 * t + 8];
        uint32_t al0 = *(const uint32_t*)&Al[r0 * 132 + k0 + 2 * t];
        uint32_t al1 = *(const uint32_t*)&Al[r1 * 132 + k0 + 2 * t];
        uint32_t al2 = *(const uint32_t*)&Al[r0 * 132 + k0 + 2 * t + 8];
        uint32_t al3 = *(const uint32_t*)&Al[r1 * 132 + k0 + 2 * t + 8];
#pragma unroll
        for (int nt = 0; nt < 16; nt++) {
            int n = nt * 8 + g;
            uint2 bh = WfH[(n * 8 + ks) * 4 + t];
            uint2 bl = WfL[(n * 8 + ks) * 4 + t];
            MMA_BF16(acc[nt], ah0, ah1, ah2, ah3, bh.x, bh.y);  // ah*bh
            MMA_BF16(acc[nt], ah0, ah1, ah2, ah3, bl.x, bl.y);  // ah*bl
            MMA_BF16(acc[nt], al0, al1, al2, al3, bh.x, bh.y);  // al*bh
        }
    }

    // epilogue: bias + relu, guarded stores
    int growA = rowbase + warp * 16 + g;
#pragma unroll
    for (int nt = 0; nt < 16; nt++) {
        int c = nt * 8 + 2 * t;
        float2 bb = *(const float2*)&b[c];
        if (growA < N_NODES) {
            float2 o;
            o.x = fmaxf(acc[nt][0] + bb.x, 0.0f);
            o.y = fmaxf(acc[nt][1] + bb.y, 0.0f);
            *(float2*)&out[(size_t)growA * 128 + c] = o;
        }
        int grow1 = growA + 8;
        if (grow1 < N_NODES) {
            float2 o;
            o.x = fmaxf(acc[nt][2] + bb.x, 0.0f);
            o.y = fmaxf(acc[nt][3] + bb.y, 0.0f);
            *(float2*)&out[(size_t)grow1 * 128 + c] = o;
        }
    }
}

extern "C" void kernel_launch(void* const* d_in, const int* in_sizes, int n_in,
                              void* d_out, int out_size) {
    // Resolve inputs by element count (robust to ordering):
    const float* x  = nullptr;
    const float* W  = nullptr;
    const float* b  = nullptr;
    const void*  ei = nullptr;
    for (int i = 0; i < n_in; i++) {
        switch (in_sizes[i]) {
            case 12800000: x  = (const float*)d_in[i]; break;
            case 16384:    W  = (const float*)d_in[i]; break;
            case 128:      b  = (const float*)d_in[i]; break;
            case 1200000:  ei = d_in[i];               break;
            default: break;
        }
    }
    float* out = (float*)d_out;
    (void)out_size;
    if (!x || !W || !b || !ei) return;

    // W split (independent of everything else)
    k_wsplit<<<(128 * 128 + 255) / 256, 256>>>(W);

    // detect edge_index dtype; decode + degree scatter (deg pre-init 1.0)
    k_or_init<<<1, 32>>>();
    k_deg_init<<<(N_NODES + 255) / 256, 256>>>();
    k_scan_odd<<<(N_EDGES + 255) / 256, 256>>>((const unsigned int*)ei);
    k_decode_deg<<<(N_EDGES + 255) / 256, 256>>>((const int*)ei);
    k_dinv<<<(N_NODES + 255) / 256, 256>>>();

    // aggx = x * dinv^2   (self-loop contribution)
    {
        long long total = (long long)N_NODES * 32;
        k_init_aggx<<<(int)((total + 255) / 256), 256>>>((const float4*)x);
    }

    // aggx[dst] += x[src] * dinv[src]*dinv[dst]   (warp per edge, red.v4)
    {
        long long total = (long long)N_EDGES * 32;
        k_edge_scatter<<<(int)((total + 255) / 256), 256>>>((const float4*)x);
    }

    // out = relu(aggx @ W + b)  — bf16x3 tensor-core GEMM
    cudaFuncSetAttribute(k_gemm_relu,
                         cudaFuncAttributeMaxDynamicSharedMemorySize, SM_TOTAL);
    k_gemm_relu<<<NBLK, 256, SM_TOTAL>>>(b, out);
}